// round 1
// baseline (speedup 1.0000x reference)
#include <cuda_runtime.h>

#define NN 100000
#define EE 1700000
#define NEG_INF -1e30f

// ---------------- device scratch (static, no allocation) ----------------
__device__ float g_h1[NN * 64];     // layer1 fc output (pre-bias, pre-relu)
__device__ float g_out1[NN * 64];   // layer1 final output (relu(agg+b))
__device__ float g_h2[NN * 32];     // layer2 fc output
__device__ float g_el1[NN * 2];
__device__ float g_er1[NN * 2];
__device__ float g_el2[NN];
__device__ float g_er2[NN];
__device__ int   g_rowptr[NN + 1];
__device__ int   g_cursor[NN];
__device__ int   g_esrc[EE];
__device__ int   g_is64;            // 1 if src/dst are int64, 0 if int32

// read index i from an index array that may be int32 or int64 (little-endian, values < 2^31)
__device__ __forceinline__ int ld_idx(const int* __restrict__ p, int i) {
    return p[(size_t)i << g_is64];
}

// ---------------- index dtype detection ----------------
__global__ void k_detect(const int* __restrict__ dst) {
    if (blockIdx.x == 0 && threadIdx.x == 0) {
        // if int64: every odd 32-bit word is a zero high-half.
        // if int32: odd words are random dst values in [0,100000) -> ~never all zero.
        int all0 = 1;
        for (int j = 1; j < 32; j += 2)
            if (dst[j] != 0) all0 = 0;
        g_is64 = all0;
    }
}

// ---------------- CSR build ----------------
__global__ void k_zero() {
    int i = blockIdx.x * blockDim.x + threadIdx.x;
    if (i <= NN) g_rowptr[i] = 0;
}

__global__ void k_count(const int* __restrict__ dst, int E) {
    int i = blockIdx.x * blockDim.x + threadIdx.x;
    int stride = gridDim.x * blockDim.x;
    for (; i < E; i += stride)
        atomicAdd(&g_rowptr[ld_idx(dst, i)], 1);
}

__global__ void k_scan() {
    __shared__ int sh[1024];
    const int T = 1024;
    const int chunk = (NN + T - 1) / T;  // 98
    int t = threadIdx.x;
    int beg = t * chunk;
    int end = min(beg + chunk, NN);
    int s = 0;
    for (int i = beg; i < end; i++) s += g_rowptr[i];
    sh[t] = s;
    __syncthreads();
    // Hillis-Steele inclusive scan
    for (int off = 1; off < T; off <<= 1) {
        int v = (t >= off) ? sh[t - off] : 0;
        __syncthreads();
        sh[t] += v;
        __syncthreads();
    }
    int run = (t == 0) ? 0 : sh[t - 1];
    for (int i = beg; i < end; i++) {
        int c = g_rowptr[i];
        g_rowptr[i] = run;
        g_cursor[i] = run;
        run += c;
    }
    if (t == T - 1) g_rowptr[NN] = sh[T - 1];
}

__global__ void k_fill(const int* __restrict__ src, const int* __restrict__ dst, int E) {
    int i = blockIdx.x * blockDim.x + threadIdx.x;
    int stride = gridDim.x * blockDim.x;
    for (; i < E; i += stride) {
        int d = ld_idx(dst, i);
        int pos = atomicAdd(&g_cursor[d], 1);
        g_esrc[pos] = ld_idx(src, i);
    }
}

// ---------------- layer 1 GEMM: h1 = feat @ W1, + attention-vector dots ----------------
// warp per row; lane owns output cols (2*lane, 2*lane+1). head = lane<16 ? 0 : 1.
__global__ void k_gemm1(const float* __restrict__ feat, const float* __restrict__ W1,
                        const float* __restrict__ al, const float* __restrict__ ar) {
    __shared__ float sW[128 * 64];
    for (int i = threadIdx.x; i < 128 * 64; i += blockDim.x) sW[i] = W1[i];
    __syncthreads();

    int lane = threadIdx.x & 31;
    int warp = (blockIdx.x * blockDim.x + threadIdx.x) >> 5;
    int nw = (gridDim.x * blockDim.x) >> 5;

    float alA = al[2 * lane], alB = al[2 * lane + 1];
    float arA = ar[2 * lane], arB = ar[2 * lane + 1];
    const float2* sW2 = (const float2*)sW;

    for (int row = warp; row < NN; row += nw) {
        const float4* f4 = (const float4*)(feat + (size_t)row * 128);
        float a0 = 0.f, a1 = 0.f;
#pragma unroll
        for (int k4 = 0; k4 < 32; k4++) {
            float4 f = __ldg(f4 + k4);
            float2 w;
            w = sW2[(4 * k4 + 0) * 32 + lane]; a0 += f.x * w.x; a1 += f.x * w.y;
            w = sW2[(4 * k4 + 1) * 32 + lane]; a0 += f.y * w.x; a1 += f.y * w.y;
            w = sW2[(4 * k4 + 2) * 32 + lane]; a0 += f.z * w.x; a1 += f.z * w.y;
            w = sW2[(4 * k4 + 3) * 32 + lane]; a0 += f.w * w.x; a1 += f.w * w.y;
        }
        *(float2*)&g_h1[(size_t)row * 64 + 2 * lane] = make_float2(a0, a1);

        // el/er epilogue: half-warp reductions (lanes 0-15 -> head0, 16-31 -> head1)
        float pl = a0 * alA + a1 * alB;
        float pr = a0 * arA + a1 * arB;
#pragma unroll
        for (int off = 8; off; off >>= 1) {
            pl += __shfl_xor_sync(0xffffffffu, pl, off);
            pr += __shfl_xor_sync(0xffffffffu, pr, off);
        }
        if (lane == 0)  { g_el1[2 * row] = pl;     g_er1[2 * row] = pr; }
        if (lane == 16) { g_el1[2 * row + 1] = pl; g_er1[2 * row + 1] = pr; }
    }
}

// ---------------- layer 1 aggregation: warp per dst node, online softmax ----------------
__global__ void k_agg1(const float* __restrict__ b1) {
    int lane = threadIdx.x & 31;
    int warp = (blockIdx.x * blockDim.x + threadIdx.x) >> 5;
    int nw = (gridDim.x * blockDim.x) >> 5;
    int head = lane >> 4;
    float bA = b1[2 * lane], bB = b1[2 * lane + 1];

    for (int v = warp; v < NN; v += nw) {
        int r0 = g_rowptr[v], r1 = g_rowptr[v + 1];
        float er = g_er1[2 * v + head];
        float m = NEG_INF, ssum = 0.f, accA = 0.f, accB = 0.f;
        for (int j = r0; j < r1; j++) {
            int s = g_esrc[j];
            float e = g_el1[2 * s + head] + er;
            e = e > 0.f ? e : 0.2f * e;                 // leaky_relu(0.2)
            float2 h = *(const float2*)&g_h1[(size_t)s * 64 + 2 * lane];
            float nm = fmaxf(m, e);
            float c = __expf(m - nm);
            float w = __expf(e - nm);
            ssum = ssum * c + w;
            accA = accA * c + w * h.x;
            accB = accB * c + w * h.y;
            m = nm;
        }
        float inv = 1.f / ssum;
        float o0 = fmaxf(accA * inv + bA, 0.f);
        float o1 = fmaxf(accB * inv + bB, 0.f);
        *(float2*)&g_out1[(size_t)v * 64 + 2 * lane] = make_float2(o0, o1);
    }
}

// ---------------- layer 2 GEMM: h2 = out1 @ W2, + attention dots ----------------
__global__ void k_gemm2(const float* __restrict__ W2, const float* __restrict__ al,
                        const float* __restrict__ ar) {
    __shared__ float sW[64 * 32];
    for (int i = threadIdx.x; i < 64 * 32; i += blockDim.x) sW[i] = W2[i];
    __syncthreads();

    int lane = threadIdx.x & 31;
    int warp = (blockIdx.x * blockDim.x + threadIdx.x) >> 5;
    int nw = (gridDim.x * blockDim.x) >> 5;
    float alv = al[lane], arv = ar[lane];

    for (int row = warp; row < NN; row += nw) {
        const float4* f4 = (const float4*)(g_out1 + (size_t)row * 64);
        float acc = 0.f;
#pragma unroll
        for (int k4 = 0; k4 < 16; k4++) {
            float4 f = f4[k4];
            acc += f.x * sW[(4 * k4 + 0) * 32 + lane];
            acc += f.y * sW[(4 * k4 + 1) * 32 + lane];
            acc += f.z * sW[(4 * k4 + 2) * 32 + lane];
            acc += f.w * sW[(4 * k4 + 3) * 32 + lane];
        }
        g_h2[(size_t)row * 32 + lane] = acc;

        float pl = acc * alv;
        float pr = acc * arv;
#pragma unroll
        for (int off = 16; off; off >>= 1) {
            pl += __shfl_xor_sync(0xffffffffu, pl, off);
            pr += __shfl_xor_sync(0xffffffffu, pr, off);
        }
        if (lane == 0) { g_el2[row] = pl; g_er2[row] = pr; }
    }
}

// ---------------- layer 2 aggregation -> final output ----------------
__global__ void k_agg2(const float* __restrict__ b2, float* __restrict__ out) {
    int lane = threadIdx.x & 31;
    int warp = (blockIdx.x * blockDim.x + threadIdx.x) >> 5;
    int nw = (gridDim.x * blockDim.x) >> 5;
    float bv = b2[lane];

    for (int v = warp; v < NN; v += nw) {
        int r0 = g_rowptr[v], r1 = g_rowptr[v + 1];
        float er = g_er2[v];
        float m = NEG_INF, ssum = 0.f, acc = 0.f;
        for (int j = r0; j < r1; j++) {
            int s = g_esrc[j];
            float e = g_el2[s] + er;
            e = e > 0.f ? e : 0.2f * e;
            float h = g_h2[(size_t)s * 32 + lane];
            float nm = fmaxf(m, e);
            float c = __expf(m - nm);
            float w = __expf(e - nm);
            ssum = ssum * c + w;
            acc = acc * c + w * h;
            m = nm;
        }
        out[(size_t)v * 32 + lane] = fmaxf(acc / ssum + bv, 0.f);
    }
}

// ---------------- launch ----------------
extern "C" void kernel_launch(void* const* d_in, const int* in_sizes, int n_in,
                              void* d_out, int out_size) {
    const float* feat = (const float*)d_in[0];
    const float* W1   = (const float*)d_in[1];
    const float* al1  = (const float*)d_in[2];
    const float* ar1  = (const float*)d_in[3];
    const float* b1   = (const float*)d_in[4];
    const float* W2   = (const float*)d_in[5];
    const float* al2  = (const float*)d_in[6];
    const float* ar2  = (const float*)d_in[7];
    const float* b2   = (const float*)d_in[8];
    const int*   src  = (const int*)d_in[9];
    const int*   dst  = (const int*)d_in[10];
    int E = in_sizes[9];
    if (E > EE) E = EE;
    float* out = (float*)d_out;

    k_detect<<<1, 32>>>(dst);
    k_zero<<<(NN + 1 + 255) / 256, 256>>>();
    k_count<<<1024, 256>>>(dst, E);
    k_scan<<<1, 1024>>>();
    k_fill<<<1024, 256>>>(src, dst, E);

    k_gemm1<<<592, 256>>>(feat, W1, al1, ar1);
    k_agg1<<<1184, 256>>>(b1);
    k_gemm2<<<592, 256>>>(W2, al2, ar2);
    k_agg2<<<1184, 256>>>(b2, out);
}

// round 2
// speedup vs baseline: 1.3624x; 1.3624x over previous
#include <cuda_runtime.h>

#define NN 100000
#define EE 1700000
#define NEG_INF -1e30f
#define SCAN_B 98
#define SCAN_T 1024

// ---------------- device scratch (static, no allocation) ----------------
__device__ float g_h1[NN * 64];     // layer1 fc output (pre-bias, pre-relu)
__device__ float g_out1[NN * 64];   // layer1 final output (relu(agg+b))
__device__ float g_h2[NN * 32];     // layer2 fc output
__device__ float g_el1[NN * 2];
__device__ float g_er1[NN * 2];
__device__ float g_el2[NN];
__device__ float g_er2[NN];
__device__ int   g_rowptr[NN + 1];
__device__ int   g_cursor[NN];
__device__ int   g_esrc[EE];
__device__ int   g_incl[SCAN_B * SCAN_T];
__device__ int   g_bsum[SCAN_B];
__device__ int   g_boff[SCAN_B];
__device__ int   g_is64;            // 1 if src/dst are int64, 0 if int32

// read index i from an index array that may be int32 or int64 (little-endian, values < 2^31)
__device__ __forceinline__ int ld_idx(const int* __restrict__ p, int i) {
    return p[(size_t)i << g_is64];
}

// ---------------- zero counters + index dtype detection (fused) ----------------
__global__ void k_zero(const int* __restrict__ dst) {
    int i = blockIdx.x * blockDim.x + threadIdx.x;
    if (i <= NN) g_rowptr[i] = 0;
    if (i == 0) {
        // if int64: every odd 32-bit word is a zero high-half.
        int all0 = 1;
        for (int j = 1; j < 32; j += 2)
            if (dst[j] != 0) all0 = 0;
        g_is64 = all0;
    }
}

__global__ void k_count(const int* __restrict__ dst, int E) {
    int i = blockIdx.x * blockDim.x + threadIdx.x;
    int stride = gridDim.x * blockDim.x;
    for (; i < E; i += stride)
        atomicAdd(&g_rowptr[ld_idx(dst, i)], 1);
}

// ---------------- two-level scan ----------------
// pass 1: per-block inclusive scan of counts (98 blocks x 1024)
__global__ void k_blockscan() {
    __shared__ int sh[SCAN_T];
    int t = threadIdx.x;
    int i = blockIdx.x * SCAN_T + t;
    int c = (i < NN) ? g_rowptr[i] : 0;
    sh[t] = c;
    __syncthreads();
#pragma unroll
    for (int off = 1; off < SCAN_T; off <<= 1) {
        int v = (t >= off) ? sh[t - off] : 0;
        __syncthreads();
        sh[t] += v;
        __syncthreads();
    }
    g_incl[i] = sh[t];
    if (t == SCAN_T - 1) g_bsum[blockIdx.x] = sh[t];
}

// pass 2: scan the 98 block sums (1 block, 128 threads)
__global__ void k_scanbsum(int E) {
    __shared__ int sh[128];
    int t = threadIdx.x;
    sh[t] = (t < SCAN_B) ? g_bsum[t] : 0;
    __syncthreads();
#pragma unroll
    for (int off = 1; off < 128; off <<= 1) {
        int v = (t >= off) ? sh[t - off] : 0;
        __syncthreads();
        sh[t] += v;
        __syncthreads();
    }
    if (t < SCAN_B) g_boff[t] = (t == 0) ? 0 : sh[t - 1];
    if (t == 0) g_rowptr[NN] = E;
}

// pass 3: exclusive = inclusive - count + block_offset; init cursor
__global__ void k_finalize() {
    int t = threadIdx.x;
    int i = blockIdx.x * SCAN_T + t;
    if (i < NN) {
        int c = g_rowptr[i];
        int v = g_incl[i] - c + g_boff[blockIdx.x];
        g_rowptr[i] = v;
        g_cursor[i] = v;
    }
}

__global__ void k_fill(const int* __restrict__ src, const int* __restrict__ dst, int E) {
    int i = blockIdx.x * blockDim.x + threadIdx.x;
    int stride = gridDim.x * blockDim.x;
    for (; i < E; i += stride) {
        int d = ld_idx(dst, i);
        int pos = atomicAdd(&g_cursor[d], 1);
        g_esrc[pos] = ld_idx(src, i);
    }
}

// ---------------- layer 1 GEMM: h1 = feat @ W1, + attention-vector dots ----------------
// warp per row; lane owns output cols (2*lane, 2*lane+1). head = lane<16 ? 0 : 1.
__global__ void k_gemm1(const float* __restrict__ feat, const float* __restrict__ W1,
                        const float* __restrict__ al, const float* __restrict__ ar) {
    __shared__ float sW[128 * 64];
    for (int i = threadIdx.x; i < 128 * 64; i += blockDim.x) sW[i] = W1[i];
    __syncthreads();

    int lane = threadIdx.x & 31;
    int warp = (blockIdx.x * blockDim.x + threadIdx.x) >> 5;
    int nw = (gridDim.x * blockDim.x) >> 5;

    float alA = al[2 * lane], alB = al[2 * lane + 1];
    float arA = ar[2 * lane], arB = ar[2 * lane + 1];
    const float2* sW2 = (const float2*)sW;

    for (int row = warp; row < NN; row += nw) {
        const float4* f4 = (const float4*)(feat + (size_t)row * 128);
        float a0 = 0.f, a1 = 0.f;
#pragma unroll
        for (int k4 = 0; k4 < 32; k4++) {
            float4 f = __ldg(f4 + k4);
            float2 w;
            w = sW2[(4 * k4 + 0) * 32 + lane]; a0 += f.x * w.x; a1 += f.x * w.y;
            w = sW2[(4 * k4 + 1) * 32 + lane]; a0 += f.y * w.x; a1 += f.y * w.y;
            w = sW2[(4 * k4 + 2) * 32 + lane]; a0 += f.z * w.x; a1 += f.z * w.y;
            w = sW2[(4 * k4 + 3) * 32 + lane]; a0 += f.w * w.x; a1 += f.w * w.y;
        }
        *(float2*)&g_h1[(size_t)row * 64 + 2 * lane] = make_float2(a0, a1);

        // el/er epilogue: half-warp reductions (lanes 0-15 -> head0, 16-31 -> head1)
        float pl = a0 * alA + a1 * alB;
        float pr = a0 * arA + a1 * arB;
#pragma unroll
        for (int off = 8; off; off >>= 1) {
            pl += __shfl_xor_sync(0xffffffffu, pl, off);
            pr += __shfl_xor_sync(0xffffffffu, pr, off);
        }
        if (lane == 0)  { g_el1[2 * row] = pl;     g_er1[2 * row] = pr; }
        if (lane == 16) { g_el1[2 * row + 1] = pl; g_er1[2 * row + 1] = pr; }
    }
}

// ---------------- layer 1 aggregation: warp per dst node, online softmax ----------------
__global__ void k_agg1(const float* __restrict__ b1) {
    int lane = threadIdx.x & 31;
    int warp = (blockIdx.x * blockDim.x + threadIdx.x) >> 5;
    int nw = (gridDim.x * blockDim.x) >> 5;
    int head = lane >> 4;
    float bA = b1[2 * lane], bB = b1[2 * lane + 1];

    for (int v = warp; v < NN; v += nw) {
        int r0 = g_rowptr[v], r1 = g_rowptr[v + 1];
        float er = g_er1[2 * v + head];
        float m = NEG_INF, ssum = 0.f, accA = 0.f, accB = 0.f;
        for (int j = r0; j < r1; j++) {
            int s = g_esrc[j];
            float e = g_el1[2 * s + head] + er;
            e = e > 0.f ? e : 0.2f * e;                 // leaky_relu(0.2)
            float2 h = *(const float2*)&g_h1[(size_t)s * 64 + 2 * lane];
            float nm = fmaxf(m, e);
            float c = __expf(m - nm);
            float w = __expf(e - nm);
            ssum = ssum * c + w;
            accA = accA * c + w * h.x;
            accB = accB * c + w * h.y;
            m = nm;
        }
        float inv = 1.f / ssum;
        float o0 = fmaxf(accA * inv + bA, 0.f);
        float o1 = fmaxf(accB * inv + bB, 0.f);
        *(float2*)&g_out1[(size_t)v * 64 + 2 * lane] = make_float2(o0, o1);
    }
}

// ---------------- layer 2 GEMM: h2 = out1 @ W2, + attention dots ----------------
__global__ void k_gemm2(const float* __restrict__ W2, const float* __restrict__ al,
                        const float* __restrict__ ar) {
    __shared__ float sW[64 * 32];
    for (int i = threadIdx.x; i < 64 * 32; i += blockDim.x) sW[i] = W2[i];
    __syncthreads();

    int lane = threadIdx.x & 31;
    int warp = (blockIdx.x * blockDim.x + threadIdx.x) >> 5;
    int nw = (gridDim.x * blockDim.x) >> 5;
    float alv = al[lane], arv = ar[lane];

    for (int row = warp; row < NN; row += nw) {
        const float4* f4 = (const float4*)(g_out1 + (size_t)row * 64);
        float acc = 0.f;
#pragma unroll
        for (int k4 = 0; k4 < 16; k4++) {
            float4 f = f4[k4];
            acc += f.x * sW[(4 * k4 + 0) * 32 + lane];
            acc += f.y * sW[(4 * k4 + 1) * 32 + lane];
            acc += f.z * sW[(4 * k4 + 2) * 32 + lane];
            acc += f.w * sW[(4 * k4 + 3) * 32 + lane];
        }
        g_h2[(size_t)row * 32 + lane] = acc;

        float pl = acc * alv;
        float pr = acc * arv;
#pragma unroll
        for (int off = 16; off; off >>= 1) {
            pl += __shfl_xor_sync(0xffffffffu, pl, off);
            pr += __shfl_xor_sync(0xffffffffu, pr, off);
        }
        if (lane == 0) { g_el2[row] = pl; g_er2[row] = pr; }
    }
}

// ---------------- layer 2 aggregation -> final output ----------------
__global__ void k_agg2(const float* __restrict__ b2, float* __restrict__ out) {
    int lane = threadIdx.x & 31;
    int warp = (blockIdx.x * blockDim.x + threadIdx.x) >> 5;
    int nw = (gridDim.x * blockDim.x) >> 5;
    float bv = b2[lane];

    for (int v = warp; v < NN; v += nw) {
        int r0 = g_rowptr[v], r1 = g_rowptr[v + 1];
        float er = g_er2[v];
        float m = NEG_INF, ssum = 0.f, acc = 0.f;
        for (int j = r0; j < r1; j++) {
            int s = g_esrc[j];
            float e = g_el2[s] + er;
            e = e > 0.f ? e : 0.2f * e;
            float h = g_h2[(size_t)s * 32 + lane];
            float nm = fmaxf(m, e);
            float c = __expf(m - nm);
            float w = __expf(e - nm);
            ssum = ssum * c + w;
            acc = acc * c + w * h;
            m = nm;
        }
        out[(size_t)v * 32 + lane] = fmaxf(acc / ssum + bv, 0.f);
    }
}

// ---------------- launch ----------------
extern "C" void kernel_launch(void* const* d_in, const int* in_sizes, int n_in,
                              void* d_out, int out_size) {
    const float* feat = (const float*)d_in[0];
    const float* W1   = (const float*)d_in[1];
    const float* al1  = (const float*)d_in[2];
    const float* ar1  = (const float*)d_in[3];
    const float* b1   = (const float*)d_in[4];
    const float* W2   = (const float*)d_in[5];
    const float* al2  = (const float*)d_in[6];
    const float* ar2  = (const float*)d_in[7];
    const float* b2   = (const float*)d_in[8];
    const int*   src  = (const int*)d_in[9];
    const int*   dst  = (const int*)d_in[10];
    int E = in_sizes[9];
    if (E > EE) E = EE;
    float* out = (float*)d_out;

    k_zero<<<(NN + 1 + 255) / 256, 256>>>(dst);
    k_count<<<1024, 256>>>(dst, E);
    k_blockscan<<<SCAN_B, SCAN_T>>>();
    k_scanbsum<<<1, 128>>>(E);
    k_finalize<<<SCAN_B, SCAN_T>>>();
    k_fill<<<1024, 256>>>(src, dst, E);

    k_gemm1<<<592, 256>>>(feat, W1, al1, ar1);
    k_agg1<<<1184, 256>>>(b1);
    k_gemm2<<<592, 256>>>(W2, al2, ar2);
    k_agg2<<<1184, 256>>>(b2, out);
}

// round 3
// speedup vs baseline: 1.7582x; 1.2905x over previous
#include <cuda_runtime.h>

#define NN 100000
#define EE 1700000
#define NEG_INF -1e30f
#define SCAN_B 98
#define SCAN_T 1024

// ---------------- device scratch (static, no allocation) ----------------
__device__ float g_h1[NN * 64];     // layer1 fc output (pre-bias, pre-relu)
__device__ float g_h2[NN * 32];     // layer2 fc output
__device__ float g_el1[NN * 2];
__device__ float g_er1[NN * 2];
__device__ float g_el2[NN];
__device__ float g_er2[NN];
__device__ int   g_rowptr[NN + 1];
__device__ int   g_cursor[NN];
__device__ int   g_esrc[EE];
__device__ int   g_incl[SCAN_B * SCAN_T];
__device__ int   g_bsum[SCAN_B];
__device__ int   g_boff[SCAN_B];
__device__ int   g_is64;            // 1 if src/dst are int64, 0 if int32

__device__ __forceinline__ int ld_idx(const int* __restrict__ p, int i) {
    return p[(size_t)i << g_is64];
}

// ---------------- zero counters + index dtype detection (fused) ----------------
__global__ void k_zero(const int* __restrict__ dst) {
    int i = blockIdx.x * blockDim.x + threadIdx.x;
    if (i <= NN) g_rowptr[i] = 0;
    if (i == 0) {
        int all0 = 1;
        for (int j = 1; j < 32; j += 2)
            if (dst[j] != 0) all0 = 0;
        g_is64 = all0;
    }
}

__global__ void k_count(const int* __restrict__ dst, int E) {
    int i = blockIdx.x * blockDim.x + threadIdx.x;
    int stride = gridDim.x * blockDim.x;
    for (; i < E; i += stride)
        atomicAdd(&g_rowptr[ld_idx(dst, i)], 1);
}

// ---------------- two-level scan ----------------
__global__ void k_blockscan() {
    __shared__ int sh[SCAN_T];
    int t = threadIdx.x;
    int i = blockIdx.x * SCAN_T + t;
    int c = (i < NN) ? g_rowptr[i] : 0;
    sh[t] = c;
    __syncthreads();
#pragma unroll
    for (int off = 1; off < SCAN_T; off <<= 1) {
        int v = (t >= off) ? sh[t - off] : 0;
        __syncthreads();
        sh[t] += v;
        __syncthreads();
    }
    g_incl[i] = sh[t];
    if (t == SCAN_T - 1) g_bsum[blockIdx.x] = sh[t];
}

__global__ void k_scanbsum(int E) {
    __shared__ int sh[128];
    int t = threadIdx.x;
    sh[t] = (t < SCAN_B) ? g_bsum[t] : 0;
    __syncthreads();
#pragma unroll
    for (int off = 1; off < 128; off <<= 1) {
        int v = (t >= off) ? sh[t - off] : 0;
        __syncthreads();
        sh[t] += v;
        __syncthreads();
    }
    if (t < SCAN_B) g_boff[t] = (t == 0) ? 0 : sh[t - 1];
    if (t == 0) g_rowptr[NN] = E;
}

__global__ void k_finalize() {
    int t = threadIdx.x;
    int i = blockIdx.x * SCAN_T + t;
    if (i < NN) {
        int c = g_rowptr[i];
        int v = g_incl[i] - c + g_boff[blockIdx.x];
        g_rowptr[i] = v;
        g_cursor[i] = v;
    }
}

__global__ void k_fill(const int* __restrict__ src, const int* __restrict__ dst, int E) {
    int i = blockIdx.x * blockDim.x + threadIdx.x;
    int stride = gridDim.x * blockDim.x;
    for (; i < E; i += stride) {
        int d = ld_idx(dst, i);
        int pos = atomicAdd(&g_cursor[d], 1);
        g_esrc[pos] = ld_idx(src, i);
    }
}

// ---------------- layer 1 GEMM: 4 rows per warp, weight-LDS reuse ----------------
__global__ void k_gemm1(const float* __restrict__ feat, const float* __restrict__ W1,
                        const float* __restrict__ al, const float* __restrict__ ar) {
    __shared__ float sW[128 * 64];
    for (int i = threadIdx.x; i < 128 * 64; i += blockDim.x) sW[i] = W1[i];
    __syncthreads();

    int lane = threadIdx.x & 31;
    int warp = (blockIdx.x * blockDim.x + threadIdx.x) >> 5;
    int nw = (gridDim.x * blockDim.x) >> 5;

    float alA = al[2 * lane], alB = al[2 * lane + 1];
    float arA = ar[2 * lane], arB = ar[2 * lane + 1];
    const float2* sW2 = (const float2*)sW;

    for (int r0 = warp * 4; r0 < NN; r0 += nw * 4) {   // NN % 4 == 0
        const float4* f0 = (const float4*)(feat + (size_t)(r0 + 0) * 128);
        const float4* f1 = (const float4*)(feat + (size_t)(r0 + 1) * 128);
        const float4* f2 = (const float4*)(feat + (size_t)(r0 + 2) * 128);
        const float4* f3 = (const float4*)(feat + (size_t)(r0 + 3) * 128);
        float a0x = 0.f, a0y = 0.f, a1x = 0.f, a1y = 0.f;
        float a2x = 0.f, a2y = 0.f, a3x = 0.f, a3y = 0.f;
#pragma unroll 8
        for (int k4 = 0; k4 < 32; k4++) {
            float x0[4], x1[4], x2[4], x3[4];
            *(float4*)x0 = __ldg(f0 + k4);
            *(float4*)x1 = __ldg(f1 + k4);
            *(float4*)x2 = __ldg(f2 + k4);
            *(float4*)x3 = __ldg(f3 + k4);
#pragma unroll
            for (int j = 0; j < 4; j++) {
                float2 w = sW2[(4 * k4 + j) * 32 + lane];
                a0x += x0[j] * w.x; a0y += x0[j] * w.y;
                a1x += x1[j] * w.x; a1y += x1[j] * w.y;
                a2x += x2[j] * w.x; a2y += x2[j] * w.y;
                a3x += x3[j] * w.x; a3y += x3[j] * w.y;
            }
        }
        *(float2*)&g_h1[(size_t)(r0 + 0) * 64 + 2 * lane] = make_float2(a0x, a0y);
        *(float2*)&g_h1[(size_t)(r0 + 1) * 64 + 2 * lane] = make_float2(a1x, a1y);
        *(float2*)&g_h1[(size_t)(r0 + 2) * 64 + 2 * lane] = make_float2(a2x, a2y);
        *(float2*)&g_h1[(size_t)(r0 + 3) * 64 + 2 * lane] = make_float2(a3x, a3y);

        // attention epilogue: half-warp reductions (lanes 0-15 head0, 16-31 head1)
#pragma unroll
        for (int r = 0; r < 4; r++) {
            float ax = r == 0 ? a0x : r == 1 ? a1x : r == 2 ? a2x : a3x;
            float ay = r == 0 ? a0y : r == 1 ? a1y : r == 2 ? a2y : a3y;
            float pl = ax * alA + ay * alB;
            float pr = ax * arA + ay * arB;
#pragma unroll
            for (int off = 8; off; off >>= 1) {
                pl += __shfl_xor_sync(0xffffffffu, pl, off);
                pr += __shfl_xor_sync(0xffffffffu, pr, off);
            }
            int row = r0 + r;
            if (lane == 0)  { g_el1[2 * row] = pl;     g_er1[2 * row] = pr; }
            if (lane == 16) { g_el1[2 * row + 1] = pl; g_er1[2 * row + 1] = pr; }
        }
    }
}

// ---------------- layer1 agg + layer2 GEMM fused (out1 never hits DRAM) ----------------
__global__ void k_agg12(const float* __restrict__ b1, const float* __restrict__ W2,
                        const float* __restrict__ al2, const float* __restrict__ ar2) {
    __shared__ float sW[64 * 32];
    __shared__ float srow[8][64];        // one out1 row per warp
    for (int i = threadIdx.x; i < 64 * 32; i += blockDim.x) sW[i] = W2[i];
    __syncthreads();

    int lane = threadIdx.x & 31;
    int wl = (threadIdx.x >> 5);         // warp within block
    int warp = (blockIdx.x * blockDim.x + threadIdx.x) >> 5;
    int nw = (gridDim.x * blockDim.x) >> 5;
    int head = lane >> 4;
    float bA = b1[2 * lane], bB = b1[2 * lane + 1];
    float alv = al2[lane], arv = ar2[lane];

    for (int v = warp; v < NN; v += nw) {
        int r0 = g_rowptr[v], r1 = g_rowptr[v + 1];
        float er = g_er1[2 * v + head];
        float m = NEG_INF, ssum = 0.f, accA = 0.f, accB = 0.f;
        for (int j = r0; j < r1; j++) {
            int s = g_esrc[j];
            float e = g_el1[2 * s + head] + er;
            e = e > 0.f ? e : 0.2f * e;                 // leaky_relu(0.2)
            float2 h = *(const float2*)&g_h1[(size_t)s * 64 + 2 * lane];
            float nm = fmaxf(m, e);
            float c = __expf(m - nm);
            float w = __expf(e - nm);
            ssum = ssum * c + w;
            accA = accA * c + w * h.x;
            accB = accB * c + w * h.y;
            m = nm;
        }
        float inv = 1.f / ssum;
        float o0 = fmaxf(accA * inv + bA, 0.f);         // out1[v, 2*lane]
        float o1 = fmaxf(accB * inv + bB, 0.f);         // out1[v, 2*lane+1]

        // ---- fused layer2 fc for this row ----
        srow[wl][2 * lane] = o0;
        srow[wl][2 * lane + 1] = o1;
        __syncwarp();
        float acc = 0.f;
#pragma unroll
        for (int k = 0; k < 64; k++)
            acc += srow[wl][k] * sW[k * 32 + lane];
        __syncwarp();
        g_h2[(size_t)v * 32 + lane] = acc;

        float pl = acc * alv;
        float pr = acc * arv;
#pragma unroll
        for (int off = 16; off; off >>= 1) {
            pl += __shfl_xor_sync(0xffffffffu, pl, off);
            pr += __shfl_xor_sync(0xffffffffu, pr, off);
        }
        if (lane == 0) { g_el2[v] = pl; g_er2[v] = pr; }
    }
}

// ---------------- layer 2 aggregation -> final output ----------------
__global__ void k_agg2(const float* __restrict__ b2, float* __restrict__ out) {
    int lane = threadIdx.x & 31;
    int warp = (blockIdx.x * blockDim.x + threadIdx.x) >> 5;
    int nw = (gridDim.x * blockDim.x) >> 5;
    float bv = b2[lane];

    for (int v = warp; v < NN; v += nw) {
        int r0 = g_rowptr[v], r1 = g_rowptr[v + 1];
        float er = g_er2[v];
        float m = NEG_INF, ssum = 0.f, acc = 0.f;
        for (int j = r0; j < r1; j++) {
            int s = g_esrc[j];
            float e = g_el2[s] + er;
            e = e > 0.f ? e : 0.2f * e;
            float h = g_h2[(size_t)s * 32 + lane];
            float nm = fmaxf(m, e);
            float c = __expf(m - nm);
            float w = __expf(e - nm);
            ssum = ssum * c + w;
            acc = acc * c + w * h;
            m = nm;
        }
        out[(size_t)v * 32 + lane] = fmaxf(acc / ssum + bv, 0.f);
    }
}

// ---------------- launch ----------------
extern "C" void kernel_launch(void* const* d_in, const int* in_sizes, int n_in,
                              void* d_out, int out_size) {
    const float* feat = (const float*)d_in[0];
    const float* W1   = (const float*)d_in[1];
    const float* al1  = (const float*)d_in[2];
    const float* ar1  = (const float*)d_in[3];
    const float* b1   = (const float*)d_in[4];
    const float* W2   = (const float*)d_in[5];
    const float* al2  = (const float*)d_in[6];
    const float* ar2  = (const float*)d_in[7];
    const float* b2   = (const float*)d_in[8];
    const int*   src  = (const int*)d_in[9];
    const int*   dst  = (const int*)d_in[10];
    int E = in_sizes[9];
    if (E > EE) E = EE;
    float* out = (float*)d_out;

    k_zero<<<(NN + 1 + 255) / 256, 256>>>(dst);          // 0
    k_count<<<1024, 256>>>(dst, E);                      // 1
    k_blockscan<<<SCAN_B, SCAN_T>>>();                   // 2
    k_gemm1<<<1184, 256>>>(feat, W1, al1, ar1);          // 3  <- profiled slot
    k_scanbsum<<<1, 128>>>(E);                           // 4
    k_finalize<<<SCAN_B, SCAN_T>>>();                    // 5
    k_fill<<<1024, 256>>>(src, dst, E);                  // 6
    k_agg12<<<1184, 256>>>(b1, W2, al2, ar2);            // 7
    k_agg2<<<1184, 256>>>(b2, out);                      // 8
}

// round 4
// speedup vs baseline: 1.9387x; 1.1027x over previous
#include <cuda_runtime.h>

#define NN 100000
#define EE 1700000
#define SCAN_B 98
#define SCAN_T 1024

// ---------------- device scratch (static, no allocation) ----------------
__device__ float g_h1[NN * 64];     // layer1 fc output (pre-bias, pre-relu)
__device__ float g_h2[NN * 32];     // layer2 fc output
__device__ float g_el1[NN * 2];
__device__ float g_er1[NN * 2];
__device__ float g_el2[NN];
__device__ float g_er2[NN];
__device__ int   g_rowptr[NN + 1];
__device__ int   g_cursor[NN];
__device__ int   g_esrc[EE];
__device__ int   g_incl[SCAN_B * SCAN_T];
__device__ int   g_bsum[SCAN_B];
__device__ int   g_boff[SCAN_B];
__device__ int   g_is64;            // 1 if src/dst are int64, 0 if int32

__device__ __forceinline__ int ld_idx(const int* __restrict__ p, int i) {
    return p[(size_t)i << g_is64];
}

// ---------------- zero counters + index dtype detection (fused) ----------------
__global__ void k_zero(const int* __restrict__ dst) {
    int i = blockIdx.x * blockDim.x + threadIdx.x;
    if (i <= NN) g_rowptr[i] = 0;
    if (i == 0) {
        int all0 = 1;
        for (int j = 1; j < 32; j += 2)
            if (dst[j] != 0) all0 = 0;
        g_is64 = all0;
    }
}

__global__ void k_count(const int* __restrict__ dst, int E) {
    int i = blockIdx.x * blockDim.x + threadIdx.x;
    int stride = gridDim.x * blockDim.x;
    for (; i < E; i += stride)
        atomicAdd(&g_rowptr[ld_idx(dst, i)], 1);
}

// ---------------- two-level scan ----------------
__global__ void k_blockscan() {
    __shared__ int sh[SCAN_T];
    int t = threadIdx.x;
    int i = blockIdx.x * SCAN_T + t;
    int c = (i < NN) ? g_rowptr[i] : 0;
    sh[t] = c;
    __syncthreads();
#pragma unroll
    for (int off = 1; off < SCAN_T; off <<= 1) {
        int v = (t >= off) ? sh[t - off] : 0;
        __syncthreads();
        sh[t] += v;
        __syncthreads();
    }
    g_incl[i] = sh[t];
    if (t == SCAN_T - 1) g_bsum[blockIdx.x] = sh[t];
}

__global__ void k_scanbsum(int E) {
    __shared__ int sh[128];
    int t = threadIdx.x;
    sh[t] = (t < SCAN_B) ? g_bsum[t] : 0;
    __syncthreads();
#pragma unroll
    for (int off = 1; off < 128; off <<= 1) {
        int v = (t >= off) ? sh[t - off] : 0;
        __syncthreads();
        sh[t] += v;
        __syncthreads();
    }
    if (t < SCAN_B) g_boff[t] = (t == 0) ? 0 : sh[t - 1];
    if (t == 0) g_rowptr[NN] = E;
}

__global__ void k_finalize() {
    int t = threadIdx.x;
    int i = blockIdx.x * SCAN_T + t;
    if (i < NN) {
        int c = g_rowptr[i];
        int v = g_incl[i] - c + g_boff[blockIdx.x];
        g_rowptr[i] = v;
        g_cursor[i] = v;
    }
}

__global__ void k_fill(const int* __restrict__ src, const int* __restrict__ dst, int E) {
    int i = blockIdx.x * blockDim.x + threadIdx.x;
    int stride = gridDim.x * blockDim.x;
    for (; i < E; i += stride) {
        int d = ld_idx(dst, i);
        int pos = atomicAdd(&g_cursor[d], 1);
        g_esrc[pos] = ld_idx(src, i);
    }
}

// ---------------- layer 1 GEMM: 8 rows per warp, weight-LDS reuse ----------------
__global__ void k_gemm1(const float* __restrict__ feat, const float* __restrict__ W1,
                        const float* __restrict__ al, const float* __restrict__ ar) {
    __shared__ float sW[128 * 64];
    for (int i = threadIdx.x; i < 128 * 64; i += blockDim.x) sW[i] = W1[i];
    __syncthreads();

    int lane = threadIdx.x & 31;
    int warp = (blockIdx.x * blockDim.x + threadIdx.x) >> 5;
    int nw = (gridDim.x * blockDim.x) >> 5;

    float alA = al[2 * lane], alB = al[2 * lane + 1];
    float arA = ar[2 * lane], arB = ar[2 * lane + 1];
    const float2* sW2 = (const float2*)sW;

    for (int r0 = warp * 8; r0 < NN; r0 += nw * 8) {   // NN % 8 == 0
        float ax[8], ay[8];
#pragma unroll
        for (int r = 0; r < 8; r++) { ax[r] = 0.f; ay[r] = 0.f; }

#pragma unroll 4
        for (int k4 = 0; k4 < 32; k4++) {
            float x[8][4];
#pragma unroll
            for (int r = 0; r < 8; r++)
                *(float4*)x[r] = __ldg((const float4*)(feat + (size_t)(r0 + r) * 128) + k4);
#pragma unroll
            for (int j = 0; j < 4; j++) {
                float2 w = sW2[(4 * k4 + j) * 32 + lane];
#pragma unroll
                for (int r = 0; r < 8; r++) {
                    ax[r] += x[r][j] * w.x;
                    ay[r] += x[r][j] * w.y;
                }
            }
        }

#pragma unroll
        for (int r = 0; r < 8; r++)
            *(float2*)&g_h1[(size_t)(r0 + r) * 64 + 2 * lane] = make_float2(ax[r], ay[r]);

        // attention epilogue: half-warp reductions (lanes 0-15 head0, 16-31 head1)
#pragma unroll
        for (int r = 0; r < 8; r++) {
            float pl = ax[r] * alA + ay[r] * alB;
            float pr = ax[r] * arA + ay[r] * arB;
#pragma unroll
            for (int off = 8; off; off >>= 1) {
                pl += __shfl_xor_sync(0xffffffffu, pl, off);
                pr += __shfl_xor_sync(0xffffffffu, pr, off);
            }
            int row = r0 + r;
            if (lane == 0)  { g_el1[2 * row] = pl;     g_er1[2 * row] = pr; }
            if (lane == 16) { g_el1[2 * row + 1] = pl; g_er1[2 * row + 1] = pr; }
        }
    }
}

// ---------------- layer1 agg + layer2 GEMM fused (out1 never hits DRAM) ----------------
// plain exp (no max-shift): scores bounded, softmax is shift-invariant.
__global__ void k_agg12(const float* __restrict__ b1, const float* __restrict__ W2,
                        const float* __restrict__ al2, const float* __restrict__ ar2) {
    __shared__ float sW[64 * 32];
    __shared__ float srow[8][64];        // one out1 row per warp
    for (int i = threadIdx.x; i < 64 * 32; i += blockDim.x) sW[i] = W2[i];
    __syncthreads();

    int lane = threadIdx.x & 31;
    int wl = (threadIdx.x >> 5);
    int warp = (blockIdx.x * blockDim.x + threadIdx.x) >> 5;
    int nw = (gridDim.x * blockDim.x) >> 5;
    int head = lane >> 4;
    float bA = b1[2 * lane], bB = b1[2 * lane + 1];
    float alv = al2[lane], arv = ar2[lane];

    for (int v = warp; v < NN; v += nw) {
        int r0 = g_rowptr[v], r1 = g_rowptr[v + 1];
        float er = g_er1[2 * v + head];
        float ssum = 0.f, accA = 0.f, accB = 0.f;
#pragma unroll 4
        for (int j = r0; j < r1; j++) {
            int s = g_esrc[j];
            float e = g_el1[2 * s + head] + er;
            e = e > 0.f ? e : 0.2f * e;                 // leaky_relu(0.2)
            float w = __expf(e);
            float2 h = *(const float2*)&g_h1[(size_t)s * 64 + 2 * lane];
            ssum += w;
            accA += w * h.x;
            accB += w * h.y;
        }
        float inv = 1.f / ssum;
        float o0 = fmaxf(accA * inv + bA, 0.f);
        float o1 = fmaxf(accB * inv + bB, 0.f);

        // ---- fused layer2 fc for this row ----
        srow[wl][2 * lane] = o0;
        srow[wl][2 * lane + 1] = o1;
        __syncwarp();
        float acc = 0.f;
#pragma unroll
        for (int k = 0; k < 64; k++)
            acc += srow[wl][k] * sW[k * 32 + lane];
        __syncwarp();
        g_h2[(size_t)v * 32 + lane] = acc;

        float pl = acc * alv;
        float pr = acc * arv;
#pragma unroll
        for (int off = 16; off; off >>= 1) {
            pl += __shfl_xor_sync(0xffffffffu, pl, off);
            pr += __shfl_xor_sync(0xffffffffu, pr, off);
        }
        if (lane == 0) { g_el2[v] = pl; g_er2[v] = pr; }
    }
}

// ---------------- layer 2 aggregation -> final output ----------------
__global__ void k_agg2(const float* __restrict__ b2, float* __restrict__ out) {
    int lane = threadIdx.x & 31;
    int warp = (blockIdx.x * blockDim.x + threadIdx.x) >> 5;
    int nw = (gridDim.x * blockDim.x) >> 5;
    float bv = b2[lane];

    for (int v = warp; v < NN; v += nw) {
        int r0 = g_rowptr[v], r1 = g_rowptr[v + 1];
        float er = g_er2[v];
        float ssum = 0.f, acc = 0.f;
#pragma unroll 4
        for (int j = r0; j < r1; j++) {
            int s = g_esrc[j];
            float e = g_el2[s] + er;
            e = e > 0.f ? e : 0.2f * e;
            float w = __expf(e);
            float h = g_h2[(size_t)s * 32 + lane];
            ssum += w;
            acc += w * h;
        }
        out[(size_t)v * 32 + lane] = fmaxf(acc / ssum + bv, 0.f);
    }
}

// ---------------- launch ----------------
extern "C" void kernel_launch(void* const* d_in, const int* in_sizes, int n_in,
                              void* d_out, int out_size) {
    const float* feat = (const float*)d_in[0];
    const float* W1   = (const float*)d_in[1];
    const float* al1  = (const float*)d_in[2];
    const float* ar1  = (const float*)d_in[3];
    const float* b1   = (const float*)d_in[4];
    const float* W2   = (const float*)d_in[5];
    const float* al2  = (const float*)d_in[6];
    const float* ar2  = (const float*)d_in[7];
    const float* b2   = (const float*)d_in[8];
    const int*   src  = (const int*)d_in[9];
    const int*   dst  = (const int*)d_in[10];
    int E = in_sizes[9];
    if (E > EE) E = EE;
    float* out = (float*)d_out;

    k_zero<<<(NN + 1 + 255) / 256, 256>>>(dst);          // 0
    k_count<<<1024, 256>>>(dst, E);                      // 1
    k_blockscan<<<SCAN_B, SCAN_T>>>();                   // 2
    k_gemm1<<<1568, 256>>>(feat, W1, al1, ar1);          // 3  <- profiled slot
    k_scanbsum<<<1, 128>>>(E);                           // 4
    k_finalize<<<SCAN_B, SCAN_T>>>();                    // 5
    k_fill<<<1024, 256>>>(src, dst, E);                  // 6
    k_agg12<<<1184, 256>>>(b1, W2, al2, ar2);            // 7
    k_agg2<<<1184, 256>>>(b2, out);                      // 8
}

// round 5
// speedup vs baseline: 2.1672x; 1.1179x over previous
#include <cuda_runtime.h>

#define NN 100000
#define EE 1700000
#define SCAN_B 98
#define SCAN_T 1024

typedef unsigned long long ull;

// ---------------- device scratch (static, no allocation) ----------------
__device__ float g_h1[NN * 64];
__device__ float g_h2[NN * 32];
__device__ float g_el1[NN * 2];
__device__ float g_er1[NN * 2];
__device__ float g_el2[NN];
__device__ float g_er2[NN];
__device__ int   g_rowptr[NN + 1];
__device__ int   g_cursor[NN];
__device__ int   g_esrc[EE];
__device__ int   g_incl[SCAN_B * SCAN_T];
__device__ int   g_bsum[SCAN_B];
__device__ int   g_boff[SCAN_B];
__device__ int   g_is64;

__device__ __forceinline__ int ld_idx(const int* __restrict__ p, int i) {
    return p[(size_t)i << g_is64];
}

// packed f32x2 fused multiply-add: d.lo += a.lo*b.lo, d.hi += a.hi*b.hi
__device__ __forceinline__ void fma2(ull& d, ull a, ull b) {
    asm("fma.rn.f32x2 %0, %1, %2, %0;" : "+l"(d) : "l"(a), "l"(b));
}
union F2U { ull u; float2 f; };
__device__ __forceinline__ ull pack2(float x, float y) {
    F2U t; t.f = make_float2(x, y); return t.u;
}
__device__ __forceinline__ float hsum2(ull v) {
    F2U t; t.u = v; return t.f.x + t.f.y;
}

// ---------------- zero counters + index dtype detection ----------------
__global__ void k_zero(const int* __restrict__ dst) {
    int i = blockIdx.x * blockDim.x + threadIdx.x;
    if (i <= NN) g_rowptr[i] = 0;
    if (i == 0) {
        int all0 = 1;
        for (int j = 1; j < 32; j += 2)
            if (dst[j] != 0) all0 = 0;
        g_is64 = all0;
    }
}

__global__ void k_count(const int* __restrict__ dst, int E) {
    int i = blockIdx.x * blockDim.x + threadIdx.x;
    int stride = gridDim.x * blockDim.x;
    for (; i < E; i += stride)
        atomicAdd(&g_rowptr[ld_idx(dst, i)], 1);
}

// ---------------- two-level scan ----------------
__global__ void k_blockscan() {
    __shared__ int sh[SCAN_T];
    int t = threadIdx.x;
    int i = blockIdx.x * SCAN_T + t;
    int c = (i < NN) ? g_rowptr[i] : 0;
    sh[t] = c;
    __syncthreads();
#pragma unroll
    for (int off = 1; off < SCAN_T; off <<= 1) {
        int v = (t >= off) ? sh[t - off] : 0;
        __syncthreads();
        sh[t] += v;
        __syncthreads();
    }
    g_incl[i] = sh[t];
    if (t == SCAN_T - 1) g_bsum[blockIdx.x] = sh[t];
}

__global__ void k_scanbsum(int E) {
    __shared__ int sh[128];
    int t = threadIdx.x;
    sh[t] = (t < SCAN_B) ? g_bsum[t] : 0;
    __syncthreads();
#pragma unroll
    for (int off = 1; off < 128; off <<= 1) {
        int v = (t >= off) ? sh[t - off] : 0;
        __syncthreads();
        sh[t] += v;
        __syncthreads();
    }
    if (t < SCAN_B) g_boff[t] = (t == 0) ? 0 : sh[t - 1];
    if (t == 0) g_rowptr[NN] = E;
}

__global__ void k_finalize() {
    int t = threadIdx.x;
    int i = blockIdx.x * SCAN_T + t;
    if (i < NN) {
        int c = g_rowptr[i];
        int v = g_incl[i] - c + g_boff[blockIdx.x];
        g_rowptr[i] = v;
        g_cursor[i] = v;
    }
}

__global__ void k_fill(const int* __restrict__ src, const int* __restrict__ dst, int E) {
    int i = blockIdx.x * blockDim.x + threadIdx.x;
    int stride = gridDim.x * blockDim.x;
    for (; i < E; i += stride) {
        int d = ld_idx(dst, i);
        int pos = atomicAdd(&g_cursor[d], 1);
        g_esrc[pos] = ld_idx(src, i);
    }
}

// ---------------- layer 1 GEMM: smem-staged feat + packed FFMA2 ----------------
// warp computes 8 rows; lane owns cols (2*lane, 2*lane+1).
// sWq[k4*64+c] = quad of weights {W[4k4][c],W[4k4+1][c],W[4k4+2][c],W[4k4+3][c]}
// accumulators hold (even-k, odd-k) partial sums in f32x2; horizontal add at end.
__global__ void k_gemm1(const float* __restrict__ feat, const float* __restrict__ W1,
                        const float* __restrict__ al, const float* __restrict__ ar) {
    __shared__ ulonglong2 sWq[32 * 64];                 // 32 KB
    __shared__ float sFeat[8][8][128];                  // 16 KB
    for (int e = threadIdx.x; e < 32 * 64; e += blockDim.x) {
        int k4 = e >> 6, c = e & 63;
        float w0 = W1[(4 * k4 + 0) * 64 + c];
        float w1 = W1[(4 * k4 + 1) * 64 + c];
        float w2 = W1[(4 * k4 + 2) * 64 + c];
        float w3 = W1[(4 * k4 + 3) * 64 + c];
        ulonglong2 q; q.x = pack2(w0, w1); q.y = pack2(w2, w3);
        sWq[e] = q;
    }
    __syncthreads();

    int lane = threadIdx.x & 31;
    int wl = threadIdx.x >> 5;
    int warp = (blockIdx.x * blockDim.x + threadIdx.x) >> 5;

    int r0 = warp * 8;
    if (r0 >= NN) return;

    // stage 8 feat rows: 1 coalesced LDG.128 + 1 STS.128 per row
#pragma unroll
    for (int r = 0; r < 8; r++) {
        float4 v = __ldg((const float4*)(feat + (size_t)(r0 + r) * 128) + lane);
        *(float4*)&sFeat[wl][r][4 * lane] = v;
    }
    __syncwarp();

    ull acc0[8], acc1[8];
#pragma unroll
    for (int r = 0; r < 8; r++) { acc0[r] = 0ull; acc1[r] = 0ull; }

    int c0 = 2 * lane;
#pragma unroll 4
    for (int k4 = 0; k4 < 32; k4++) {
        ulonglong2 wq0 = sWq[k4 * 64 + c0];
        ulonglong2 wq1 = sWq[k4 * 64 + c0 + 1];
#pragma unroll
        for (int r = 0; r < 8; r++) {
            ulonglong2 xq = *(const ulonglong2*)&sFeat[wl][r][4 * k4];  // broadcast LDS.128
            fma2(acc0[r], xq.x, wq0.x);
            fma2(acc0[r], xq.y, wq0.y);
            fma2(acc1[r], xq.x, wq1.x);
            fma2(acc1[r], xq.y, wq1.y);
        }
    }

    float alA = al[c0], alB = al[c0 + 1];
    float arA = ar[c0], arB = ar[c0 + 1];

#pragma unroll
    for (int r = 0; r < 8; r++) {
        float ax = hsum2(acc0[r]);
        float ay = hsum2(acc1[r]);
        *(float2*)&g_h1[(size_t)(r0 + r) * 64 + c0] = make_float2(ax, ay);

        float pl = ax * alA + ay * alB;
        float pr = ax * arA + ay * arB;
#pragma unroll
        for (int off = 8; off; off >>= 1) {
            pl += __shfl_xor_sync(0xffffffffu, pl, off);
            pr += __shfl_xor_sync(0xffffffffu, pr, off);
        }
        int row = r0 + r;
        if (lane == 0)  { g_el1[2 * row] = pl;     g_er1[2 * row] = pr; }
        if (lane == 16) { g_el1[2 * row + 1] = pl; g_er1[2 * row + 1] = pr; }
    }
}

// ---------------- layer1 agg + layer2 GEMM fused ----------------
__global__ void k_agg12(const float* __restrict__ b1, const float* __restrict__ W2,
                        const float* __restrict__ al2, const float* __restrict__ ar2) {
    __shared__ ull sW2p[32 * 32];                       // pair-packed W2, 8 KB
    __shared__ __align__(16) float srow[8][64];
    for (int e = threadIdx.x; e < 32 * 32; e += blockDim.x) {
        int k2 = e >> 5, c = e & 31;
        sW2p[e] = pack2(W2[(2 * k2) * 32 + c], W2[(2 * k2 + 1) * 32 + c]);
    }
    __syncthreads();

    int lane = threadIdx.x & 31;
    int wl = threadIdx.x >> 5;
    int warp = (blockIdx.x * blockDim.x + threadIdx.x) >> 5;
    int nw = (gridDim.x * blockDim.x) >> 5;
    int head = lane >> 4;
    float bA = b1[2 * lane], bB = b1[2 * lane + 1];
    float alv = al2[lane], arv = ar2[lane];

    for (int v = warp; v < NN; v += nw) {
        int r0 = g_rowptr[v], r1 = g_rowptr[v + 1];
        float er = g_er1[2 * v + head];
        float ssum = 0.f, accA = 0.f, accB = 0.f;
#pragma unroll 4
        for (int j = r0; j < r1; j++) {
            int s = g_esrc[j];
            float e = g_el1[2 * s + head] + er;
            e = e > 0.f ? e : 0.2f * e;                 // leaky_relu(0.2)
            float w = __expf(e);
            float2 h = *(const float2*)&g_h1[(size_t)s * 64 + 2 * lane];
            ssum += w;
            accA += w * h.x;
            accB += w * h.y;
        }
        float inv = 1.f / ssum;
        float o0 = fmaxf(accA * inv + bA, 0.f);
        float o1 = fmaxf(accB * inv + bB, 0.f);

        // fused layer2 fc: pairwise-K FFMA2
        srow[wl][2 * lane] = o0;
        srow[wl][2 * lane + 1] = o1;
        __syncwarp();
        ull accp = 0ull;
#pragma unroll
        for (int k2 = 0; k2 < 32; k2++)
            fma2(accp, *(const ull*)&srow[wl][2 * k2], sW2p[k2 * 32 + lane]);
        __syncwarp();
        float acc = hsum2(accp);
        g_h2[(size_t)v * 32 + lane] = acc;

        float pl = acc * alv;
        float pr = acc * arv;
#pragma unroll
        for (int off = 16; off; off >>= 1) {
            pl += __shfl_xor_sync(0xffffffffu, pl, off);
            pr += __shfl_xor_sync(0xffffffffu, pr, off);
        }
        if (lane == 0) { g_el2[v] = pl; g_er2[v] = pr; }
    }
}

// ---------------- layer 2 aggregation -> final output ----------------
__global__ void k_agg2(const float* __restrict__ b2, float* __restrict__ out) {
    int lane = threadIdx.x & 31;
    int warp = (blockIdx.x * blockDim.x + threadIdx.x) >> 5;
    int nw = (gridDim.x * blockDim.x) >> 5;
    float bv = b2[lane];

    for (int v = warp; v < NN; v += nw) {
        int r0 = g_rowptr[v], r1 = g_rowptr[v + 1];
        float er = g_er2[v];
        float ssum = 0.f, acc = 0.f;
#pragma unroll 4
        for (int j = r0; j < r1; j++) {
            int s = g_esrc[j];
            float e = g_el2[s] + er;
            e = e > 0.f ? e : 0.2f * e;
            float w = __expf(e);
            float h = g_h2[(size_t)s * 32 + lane];
            ssum += w;
            acc += w * h;
        }
        out[(size_t)v * 32 + lane] = fmaxf(acc / ssum + bv, 0.f);
    }
}

// ---------------- launch ----------------
extern "C" void kernel_launch(void* const* d_in, const int* in_sizes, int n_in,
                              void* d_out, int out_size) {
    const float* feat = (const float*)d_in[0];
    const float* W1   = (const float*)d_in[1];
    const float* al1  = (const float*)d_in[2];
    const float* ar1  = (const float*)d_in[3];
    const float* b1   = (const float*)d_in[4];
    const float* W2   = (const float*)d_in[5];
    const float* al2  = (const float*)d_in[6];
    const float* ar2  = (const float*)d_in[7];
    const float* b2   = (const float*)d_in[8];
    const int*   src  = (const int*)d_in[9];
    const int*   dst  = (const int*)d_in[10];
    int E = in_sizes[9];
    if (E > EE) E = EE;
    float* out = (float*)d_out;

    k_zero<<<(NN + 1 + 255) / 256, 256>>>(dst);          // 0
    k_count<<<1024, 256>>>(dst, E);                      // 1
    k_blockscan<<<SCAN_B, SCAN_T>>>();                   // 2
    k_gemm1<<<1563, 256>>>(feat, W1, al1, ar1);          // 3  <- profiled slot
    k_scanbsum<<<1, 128>>>(E);                           // 4
    k_finalize<<<SCAN_B, SCAN_T>>>();                    // 5
    k_fill<<<1024, 256>>>(src, dst, E);                  // 6
    k_agg12<<<1184, 256>>>(b1, W2, al2, ar2);            // 7
    k_agg2<<<1184, 256>>>(b2, out);                      // 8
}

// round 6
// speedup vs baseline: 2.2051x; 1.0175x over previous
#include <cuda_runtime.h>

#define NN 100000
#define EE 1700000
#define SCAN_B 98
#define SCAN_T 1024

typedef unsigned long long ull;

// ---------------- device scratch (static, no allocation) ----------------
__device__ float g_h1[NN * 64];
__device__ float g_h2[NN * 32];
__device__ float g_el1[NN * 2];
__device__ float g_er1[NN * 2];
__device__ float g_el2[NN];
__device__ float g_er2[NN];
__device__ int   g_rowptr[NN + 1];
__device__ int   g_cursor[NN];
__device__ int   g_esrc[EE];
__device__ int   g_incl[SCAN_B * SCAN_T];
__device__ int   g_bsum[SCAN_B];
__device__ int   g_boff[SCAN_B];
__device__ int   g_is64;

__device__ __forceinline__ int ld_idx(const int* __restrict__ p, int i) {
    return p[(size_t)i << g_is64];
}

__device__ __forceinline__ void fma2(ull& d, ull a, ull b) {
    asm("fma.rn.f32x2 %0, %1, %2, %0;" : "+l"(d) : "l"(a), "l"(b));
}
union F2U { ull u; float2 f; };
__device__ __forceinline__ ull pack2(float x, float y) {
    F2U t; t.f = make_float2(x, y); return t.u;
}
__device__ __forceinline__ float hsum2(ull v) {
    F2U t; t.u = v; return t.f.x + t.f.y;
}

// ---------------- zero counters + index dtype detection ----------------
__global__ void k_zero(const int* __restrict__ dst) {
    int i = blockIdx.x * blockDim.x + threadIdx.x;
    if (i <= NN) g_rowptr[i] = 0;
    if (i == 0) {
        int all0 = 1;
        for (int j = 1; j < 32; j += 2)
            if (dst[j] != 0) all0 = 0;
        g_is64 = all0;
    }
}

__global__ void k_count(const int* __restrict__ dst, int E) {
    int i = blockIdx.x * blockDim.x + threadIdx.x;
    int stride = gridDim.x * blockDim.x;
    for (; i < E; i += stride)
        atomicAdd(&g_rowptr[ld_idx(dst, i)], 1);
}

// ---------------- two-level scan ----------------
__global__ void k_blockscan() {
    __shared__ int sh[SCAN_T];
    int t = threadIdx.x;
    int i = blockIdx.x * SCAN_T + t;
    int c = (i < NN) ? g_rowptr[i] : 0;
    sh[t] = c;
    __syncthreads();
#pragma unroll
    for (int off = 1; off < SCAN_T; off <<= 1) {
        int v = (t >= off) ? sh[t - off] : 0;
        __syncthreads();
        sh[t] += v;
        __syncthreads();
    }
    g_incl[i] = sh[t];
    if (t == SCAN_T - 1) g_bsum[blockIdx.x] = sh[t];
}

__global__ void k_scanbsum(int E) {
    __shared__ int sh[128];
    int t = threadIdx.x;
    sh[t] = (t < SCAN_B) ? g_bsum[t] : 0;
    __syncthreads();
#pragma unroll
    for (int off = 1; off < 128; off <<= 1) {
        int v = (t >= off) ? sh[t - off] : 0;
        __syncthreads();
        sh[t] += v;
        __syncthreads();
    }
    if (t < SCAN_B) g_boff[t] = (t == 0) ? 0 : sh[t - 1];
    if (t == 0) g_rowptr[NN] = E;
}

__global__ void k_finalize() {
    int t = threadIdx.x;
    int i = blockIdx.x * SCAN_T + t;
    if (i < NN) {
        int c = g_rowptr[i];
        int v = g_incl[i] - c + g_boff[blockIdx.x];
        g_rowptr[i] = v;
        g_cursor[i] = v;
    }
}

__global__ void k_fill(const int* __restrict__ src, const int* __restrict__ dst, int E) {
    int i = blockIdx.x * blockDim.x + threadIdx.x;
    int stride = gridDim.x * blockDim.x;
    for (; i < E; i += stride) {
        int d = ld_idx(dst, i);
        int pos = atomicAdd(&g_cursor[d], 1);
        g_esrc[pos] = ld_idx(src, i);
    }
}

// ---------------- layer 1 GEMM: 16 rows/warp, K-split staging, FFMA2 ----------------
// block = 128 threads (4 warps). smem = 32KB weights + 16KB feat = 48KB exactly.
// lane owns cols (2*lane, 2*lane+1); accumulators in f32x2 over (even,odd) K.
__global__ void __launch_bounds__(128, 4)
k_gemm1(const float* __restrict__ feat, const float* __restrict__ W1,
        const float* __restrict__ al, const float* __restrict__ ar) {
    __shared__ ulonglong2 sWq[32 * 64];                 // 32 KB (quad-packed weights)
    __shared__ float sFeat[4][16][64];                  // 16 KB (K-half staging)

    for (int e = threadIdx.x; e < 32 * 64; e += blockDim.x) {
        int k4 = e >> 6, c = e & 63;
        ulonglong2 q;
        q.x = pack2(W1[(4 * k4 + 0) * 64 + c], W1[(4 * k4 + 1) * 64 + c]);
        q.y = pack2(W1[(4 * k4 + 2) * 64 + c], W1[(4 * k4 + 3) * 64 + c]);
        sWq[e] = q;
    }
    __syncthreads();

    int lane = threadIdx.x & 31;
    int wl = threadIdx.x >> 5;
    int warp = (blockIdx.x * blockDim.x + threadIdx.x) >> 5;
    int r0 = warp * 16;
    if (r0 >= NN) return;                               // NN % 16 == 0

    ull acc0[16], acc1[16];
#pragma unroll
    for (int r = 0; r < 16; r++) { acc0[r] = 0ull; acc1[r] = 0ull; }

    int c0 = 2 * lane;
    int lrow = lane >> 4;          // 0..1
    int lcol = lane & 15;          // 0..15

#pragma unroll
    for (int p = 0; p < 2; p++) {
        // stage K-half p for 16 rows: lane loads float4; 16 lanes cover one row-half
#pragma unroll
        for (int rr = 0; rr < 8; rr++) {
            int row = rr * 2 + lrow;
            float4 v = __ldg((const float4*)(feat + (size_t)(r0 + row) * 128 + p * 64) + lcol);
            *(float4*)&sFeat[wl][row][4 * lcol] = v;
        }
        __syncwarp();

#pragma unroll 4
        for (int kq = 0; kq < 16; kq++) {
            int k4 = p * 16 + kq;
            ulonglong2 wq0 = sWq[k4 * 64 + c0];
            ulonglong2 wq1 = sWq[k4 * 64 + c0 + 1];
#pragma unroll
            for (int r = 0; r < 16; r++) {
                ulonglong2 xq = *(const ulonglong2*)&sFeat[wl][r][4 * kq];  // broadcast
                fma2(acc0[r], xq.x, wq0.x);
                fma2(acc0[r], xq.y, wq0.y);
                fma2(acc1[r], xq.x, wq1.x);
                fma2(acc1[r], xq.y, wq1.y);
            }
        }
        __syncwarp();
    }

    float alA = al[c0], alB = al[c0 + 1];
    float arA = ar[c0], arB = ar[c0 + 1];

#pragma unroll
    for (int r = 0; r < 16; r++) {
        float ax = hsum2(acc0[r]);
        float ay = hsum2(acc1[r]);
        *(float2*)&g_h1[(size_t)(r0 + r) * 64 + c0] = make_float2(ax, ay);

        float pl = ax * alA + ay * alB;
        float pr = ax * arA + ay * arB;
#pragma unroll
        for (int off = 8; off; off >>= 1) {
            pl += __shfl_xor_sync(0xffffffffu, pl, off);
            pr += __shfl_xor_sync(0xffffffffu, pr, off);
        }
        int row = r0 + r;
        if (lane == 0)  { g_el1[2 * row] = pl;     g_er1[2 * row] = pr; }
        if (lane == 16) { g_el1[2 * row + 1] = pl; g_er1[2 * row + 1] = pr; }
    }
}

// ---------------- layer1 agg + layer2 GEMM fused ----------------
__global__ void k_agg12(const float* __restrict__ b1, const float* __restrict__ W2,
                        const float* __restrict__ al2, const float* __restrict__ ar2) {
    __shared__ ull sW2p[32 * 32];
    __shared__ __align__(16) float srow[8][64];
    for (int e = threadIdx.x; e < 32 * 32; e += blockDim.x) {
        int k2 = e >> 5, c = e & 31;
        sW2p[e] = pack2(W2[(2 * k2) * 32 + c], W2[(2 * k2 + 1) * 32 + c]);
    }
    __syncthreads();

    int lane = threadIdx.x & 31;
    int wl = threadIdx.x >> 5;
    int warp = (blockIdx.x * blockDim.x + threadIdx.x) >> 5;
    int nw = (gridDim.x * blockDim.x) >> 5;
    int head = lane >> 4;
    float bA = b1[2 * lane], bB = b1[2 * lane + 1];
    float alv = al2[lane], arv = ar2[lane];

    for (int v = warp; v < NN; v += nw) {
        int r0 = g_rowptr[v], r1 = g_rowptr[v + 1];
        float er = g_er1[2 * v + head];
        float ssum = 0.f, accA = 0.f, accB = 0.f;
#pragma unroll 4
        for (int j = r0; j < r1; j++) {
            int s = g_esrc[j];
            float e = g_el1[2 * s + head] + er;
            e = e > 0.f ? e : 0.2f * e;                 // leaky_relu(0.2)
            float w = __expf(e);
            float2 h = *(const float2*)&g_h1[(size_t)s * 64 + 2 * lane];
            ssum += w;
            accA += w * h.x;
            accB += w * h.y;
        }
        float inv = 1.f / ssum;
        float o0 = fmaxf(accA * inv + bA, 0.f);
        float o1 = fmaxf(accB * inv + bB, 0.f);

        srow[wl][2 * lane] = o0;
        srow[wl][2 * lane + 1] = o1;
        __syncwarp();
        ull accp = 0ull;
#pragma unroll
        for (int k2 = 0; k2 < 32; k2++)
            fma2(accp, *(const ull*)&srow[wl][2 * k2], sW2p[k2 * 32 + lane]);
        __syncwarp();
        float acc = hsum2(accp);
        g_h2[(size_t)v * 32 + lane] = acc;

        float pl = acc * alv;
        float pr = acc * arv;
#pragma unroll
        for (int off = 16; off; off >>= 1) {
            pl += __shfl_xor_sync(0xffffffffu, pl, off);
            pr += __shfl_xor_sync(0xffffffffu, pr, off);
        }
        if (lane == 0) { g_el2[v] = pl; g_er2[v] = pr; }
    }
}

// ---------------- layer 2 aggregation -> final output ----------------
__global__ void k_agg2(const float* __restrict__ b2, float* __restrict__ out) {
    int lane = threadIdx.x & 31;
    int warp = (blockIdx.x * blockDim.x + threadIdx.x) >> 5;
    int nw = (gridDim.x * blockDim.x) >> 5;
    float bv = b2[lane];

    for (int v = warp; v < NN; v += nw) {
        int r0 = g_rowptr[v], r1 = g_rowptr[v + 1];
        float er = g_er2[v];
        float ssum = 0.f, acc = 0.f;
#pragma unroll 4
        for (int j = r0; j < r1; j++) {
            int s = g_esrc[j];
            float e = g_el2[s] + er;
            e = e > 0.f ? e : 0.2f * e;
            float w = __expf(e);
            float h = g_h2[(size_t)s * 32 + lane];
            ssum += w;
            acc += w * h;
        }
        out[(size_t)v * 32 + lane] = fmaxf(acc / ssum + bv, 0.f);
    }
}

// ---------------- launch ----------------
extern "C" void kernel_launch(void* const* d_in, const int* in_sizes, int n_in,
                              void* d_out, int out_size) {
    const float* feat = (const float*)d_in[0];
    const float* W1   = (const float*)d_in[1];
    const float* al1  = (const float*)d_in[2];
    const float* ar1  = (const float*)d_in[3];
    const float* b1   = (const float*)d_in[4];
    const float* W2   = (const float*)d_in[5];
    const float* al2  = (const float*)d_in[6];
    const float* ar2  = (const float*)d_in[7];
    const float* b2   = (const float*)d_in[8];
    const int*   src  = (const int*)d_in[9];
    const int*   dst  = (const int*)d_in[10];
    int E = in_sizes[9];
    if (E > EE) E = EE;
    float* out = (float*)d_out;

    k_zero<<<(NN + 1 + 255) / 256, 256>>>(dst);          // 0
    k_count<<<1024, 256>>>(dst, E);                      // 1
    k_blockscan<<<SCAN_B, SCAN_T>>>();                   // 2
    k_gemm1<<<1563, 128>>>(feat, W1, al1, ar1);          // 3  <- profiled slot
    k_scanbsum<<<1, 128>>>(E);                           // 4
    k_finalize<<<SCAN_B, SCAN_T>>>();                    // 5
    k_fill<<<1024, 256>>>(src, dst, E);                  // 6
    k_agg12<<<1184, 256>>>(b1, W2, al2, ar2);            // 7
    k_agg2<<<1184, 256>>>(b2, out);                      // 8
}

// round 9
// speedup vs baseline: 2.3624x; 1.0713x over previous
#include <cuda_runtime.h>
#include <cuda_bf16.h>
#include <cstdint>

#define NN 100000
#define EE 1700000
#define SCAN_B 98
#define SCAN_T 1024

typedef unsigned long long ull;

// ---------------- device scratch (static, no allocation) ----------------
__device__ float g_h1[NN * 64];
__device__ float g_h2[NN * 32];
__device__ float g_el1[NN * 2];
__device__ float g_er1[NN * 2];
__device__ float g_el2[NN];
__device__ float g_er2[NN];
__device__ int   g_rowptr[NN + 1];
__device__ int   g_cursor[NN];
__device__ int   g_esrc[EE];
__device__ int   g_incl[SCAN_B * SCAN_T];
__device__ int   g_bsum[SCAN_B];
__device__ int   g_boff[SCAN_B];
__device__ int   g_is64;
// bf16-split weights for layer1 MMA: [n][k], n<64: W1 col n; 64..67: attn q-cols; 68..71: 0
__device__ __align__(16) unsigned short g_Wh[72 * 128];
__device__ __align__(16) unsigned short g_Wl[72 * 128];

__device__ __forceinline__ int ld_idx(const int* __restrict__ p, int i) {
    return p[(size_t)i << g_is64];
}

__device__ __forceinline__ void fma2(ull& d, ull a, ull b) {
    asm("fma.rn.f32x2 %0, %1, %2, %0;" : "+l"(d) : "l"(a), "l"(b));
}
union F2U { ull u; float2 f; };
__device__ __forceinline__ ull pack2(float x, float y) {
    F2U t; t.f = make_float2(x, y); return t.u;
}
__device__ __forceinline__ float hsum2(ull v) {
    F2U t; t.u = v; return t.f.x + t.f.y;
}

__device__ __forceinline__ uint32_t smem_u32(const void* p) {
    uint32_t a;
    asm("{ .reg .u64 t; cvta.to.shared.u64 t, %1; cvt.u32.u64 %0, t; }" : "=r"(a) : "l"(p));
    return a;
}

// ---------------- zero counters + index dtype detection ----------------
__global__ void k_zero(const int* __restrict__ dst) {
    int i = blockIdx.x * blockDim.x + threadIdx.x;
    if (i <= NN) g_rowptr[i] = 0;
    if (i == 0) {
        int all0 = 1;
        for (int j = 1; j < 32; j += 2)
            if (dst[j] != 0) all0 = 0;
        g_is64 = all0;
    }
}

__global__ void k_count(const int* __restrict__ dst, int E) {
    int i = blockIdx.x * blockDim.x + threadIdx.x;
    int stride = gridDim.x * blockDim.x;
    for (; i < E; i += stride)
        atomicAdd(&g_rowptr[ld_idx(dst, i)], 1);
}

// ---------------- W1 bf16 split + attention q-columns ----------------
__global__ void k_wsplit(const float* __restrict__ W1, const float* __restrict__ al,
                         const float* __restrict__ ar) {
    int idx = blockIdx.x * blockDim.x + threadIdx.x;
    if (idx >= 72 * 128) return;
    int n = idx >> 7, k = idx & 127;
    float w = 0.f;
    if (n < 64) {
        w = W1[k * 64 + n];
    } else if (n < 68) {
        int h = (n - 64) & 1;
        const float* v = (n < 66) ? al : ar;
        for (int d = 0; d < 32; d++)
            w += W1[k * 64 + h * 32 + d] * v[h * 32 + d];
    }
    __nv_bfloat16 hi = __float2bfloat16(w);
    __nv_bfloat16 lo = __float2bfloat16(w - __bfloat162float(hi));
    g_Wh[idx] = __bfloat16_as_ushort(hi);
    g_Wl[idx] = __bfloat16_as_ushort(lo);
}

// ---------------- two-level scan ----------------
__global__ void k_blockscan() {
    __shared__ int sh[SCAN_T];
    int t = threadIdx.x;
    int i = blockIdx.x * SCAN_T + t;
    int c = (i < NN) ? g_rowptr[i] : 0;
    sh[t] = c;
    __syncthreads();
#pragma unroll
    for (int off = 1; off < SCAN_T; off <<= 1) {
        int v = (t >= off) ? sh[t - off] : 0;
        __syncthreads();
        sh[t] += v;
        __syncthreads();
    }
    g_incl[i] = sh[t];
    if (t == SCAN_T - 1) g_bsum[blockIdx.x] = sh[t];
}

__global__ void k_scanbsum(int E) {
    __shared__ int sh[128];
    int t = threadIdx.x;
    sh[t] = (t < SCAN_B) ? g_bsum[t] : 0;
    __syncthreads();
#pragma unroll
    for (int off = 1; off < 128; off <<= 1) {
        int v = (t >= off) ? sh[t - off] : 0;
        __syncthreads();
        sh[t] += v;
        __syncthreads();
    }
    if (t < SCAN_B) g_boff[t] = (t == 0) ? 0 : sh[t - 1];
    if (t == 0) g_rowptr[NN] = E;
}

__global__ void k_finalize() {
    int t = threadIdx.x;
    int i = blockIdx.x * SCAN_T + t;
    if (i < NN) {
        int c = g_rowptr[i];
        int v = g_incl[i] - c + g_boff[blockIdx.x];
        g_rowptr[i] = v;
        g_cursor[i] = v;
    }
}

__global__ void k_fill(const int* __restrict__ src, const int* __restrict__ dst, int E) {
    int i = blockIdx.x * blockDim.x + threadIdx.x;
    int stride = gridDim.x * blockDim.x;
    for (; i < E; i += stride) {
        int d = ld_idx(dst, i);
        int pos = atomicAdd(&g_cursor[d], 1);
        g_esrc[pos] = ld_idx(src, i);
    }
}

// ---------------- layer 1 GEMM via mma.sync bf16-split ----------------
// CTA = 128 rows, 4 warps x 32 rows; D[128,72] = feat @ B^T.
// D ~= AhBh + AlBh + AhBl, fp32 accum. attn q-cols ride along as n=64..67.
// smem rows: 256B (128 bf16), XOR-16B swizzle (chunk ^= row&7).
#define SM_AH 0
#define SM_AL 32768
#define SM_BH 65536
#define SM_BL 83968
#define SM_TOT 102400

__device__ __forceinline__ uint32_t swz(uint32_t base, int row, int chunk) {
    return base + (uint32_t)row * 256u + (uint32_t)((chunk ^ (row & 7)) << 4);
}

__global__ void __launch_bounds__(128, 2)
k_gemm1(const float* __restrict__ feat) {
    extern __shared__ char smem[];
    uint32_t sb = smem_u32(smem);
    int tid = threadIdx.x;
    int w = tid >> 5;
    int lane = tid & 31;
    int tile_r0 = blockIdx.x * 128;

    // ---- stage A: 128 rows x 16 chunks, bf16 hi/lo ----
#pragma unroll
    for (int it = 0; it < 16; it++) {
        int i = it * 128 + tid;
        int row = i >> 4, chunk = i & 15;
        int grow = tile_r0 + row;
        float4 v0, v1;
        if (grow < NN) {
            const float4* fp = (const float4*)(feat + (size_t)grow * 128 + chunk * 8);
            v0 = __ldg(fp); v1 = __ldg(fp + 1);
        } else {
            v0 = make_float4(0.f, 0.f, 0.f, 0.f); v1 = v0;
        }
        float f[8] = {v0.x, v0.y, v0.z, v0.w, v1.x, v1.y, v1.z, v1.w};
        uint32_t hp[4], lp[4];
#pragma unroll
        for (int q = 0; q < 4; q++) {
            __nv_bfloat16 h0 = __float2bfloat16(f[2 * q]);
            __nv_bfloat16 h1 = __float2bfloat16(f[2 * q + 1]);
            hp[q] = ((uint32_t)__bfloat16_as_ushort(h1) << 16) | __bfloat16_as_ushort(h0);
            __nv_bfloat16 l0 = __float2bfloat16(f[2 * q] - __bfloat162float(h0));
            __nv_bfloat16 l1 = __float2bfloat16(f[2 * q + 1] - __bfloat162float(h1));
            lp[q] = ((uint32_t)__bfloat16_as_ushort(l1) << 16) | __bfloat16_as_ushort(l0);
        }
        uint32_t a = swz(0, row, chunk);
        *(uint4*)(smem + SM_AH + a) = make_uint4(hp[0], hp[1], hp[2], hp[3]);
        *(uint4*)(smem + SM_AL + a) = make_uint4(lp[0], lp[1], lp[2], lp[3]);
    }
    // ---- stage B: 72 rows x 16 chunks x 2 splits ----
#pragma unroll
    for (int it = 0; it < 18; it++) {
        int i = it * 128 + tid;
        int split = i >= 1152;
        int j = split ? i - 1152 : i;
        int row = j >> 4, chunk = j & 15;
        const uint4* src = (const uint4*)((split ? g_Wl : g_Wh) + row * 128 + chunk * 8);
        uint32_t a = swz(0, row, chunk);
        *(uint4*)(smem + (split ? SM_BL : SM_BH) + a) = __ldg(src);
    }
    __syncthreads();

    // ---- compute: warp w -> rows w*32..+31 ----
    float c[2][9][4];
#pragma unroll
    for (int h = 0; h < 2; h++)
#pragma unroll
        for (int n = 0; n < 9; n++)
#pragma unroll
            for (int q = 0; q < 4; q++) c[h][n][q] = 0.f;

#pragma unroll
    for (int p = 0; p < 3; p++) {
        uint32_t A = sb + (p == 1 ? SM_AL : SM_AH);
        uint32_t B = sb + (p == 2 ? SM_BL : SM_BH);
#pragma unroll
        for (int k = 0; k < 8; k++) {
            uint32_t a[2][4];
#pragma unroll
            for (int h = 0; h < 2; h++) {
                int r = w * 32 + h * 16 + (lane & 15);
                int ch = k * 2 + (lane >> 4);
                uint32_t addr = swz(A, r, ch);
                asm volatile("ldmatrix.sync.aligned.m8n8.x4.shared.b16 {%0,%1,%2,%3}, [%4];"
                    : "=r"(a[h][0]), "=r"(a[h][1]), "=r"(a[h][2]), "=r"(a[h][3]) : "r"(addr));
            }
#pragma unroll
            for (int n = 0; n < 9; n++) {
                int rn = n * 8 + (lane & 7);
                int cn = k * 2 + ((lane >> 3) & 1);
                uint32_t baddr = swz(B, rn, cn);
                uint32_t b0, b1;
                asm volatile("ldmatrix.sync.aligned.m8n8.x2.shared.b16 {%0,%1}, [%2];"
                    : "=r"(b0), "=r"(b1) : "r"(baddr));
#pragma unroll
                for (int h = 0; h < 2; h++) {
                    asm volatile(
                        "mma.sync.aligned.m16n8k16.row.col.f32.bf16.bf16.f32 "
                        "{%0,%1,%2,%3},{%4,%5,%6,%7},{%8,%9},{%0,%1,%2,%3};"
                        : "+f"(c[h][n][0]), "+f"(c[h][n][1]), "+f"(c[h][n][2]), "+f"(c[h][n][3])
                        : "r"(a[h][0]), "r"(a[h][1]), "r"(a[h][2]), "r"(a[h][3]),
                          "r"(b0), "r"(b1));
                }
            }
        }
    }

    // ---- epilogue: write h1 + el/er straight from fragments ----
    int qrow = lane >> 2;
    int cc = (lane & 3) * 2;
#pragma unroll
    for (int h = 0; h < 2; h++) {
        int row0 = tile_r0 + w * 32 + h * 16 + qrow;
        int row1 = row0 + 8;
#pragma unroll
        for (int n = 0; n < 8; n++) {
            if (row0 < NN)
                *(float2*)&g_h1[(size_t)row0 * 64 + n * 8 + cc] = make_float2(c[h][n][0], c[h][n][1]);
            if (row1 < NN)
                *(float2*)&g_h1[(size_t)row1 * 64 + n * 8 + cc] = make_float2(c[h][n][2], c[h][n][3]);
        }
        if ((lane & 3) == 0) {
            if (row0 < NN) *(float2*)&g_el1[2 * row0] = make_float2(c[h][8][0], c[h][8][1]);
            if (row1 < NN) *(float2*)&g_el1[2 * row1] = make_float2(c[h][8][2], c[h][8][3]);
        } else if ((lane & 3) == 1) {
            if (row0 < NN) *(float2*)&g_er1[2 * row0] = make_float2(c[h][8][0], c[h][8][1]);
            if (row1 < NN) *(float2*)&g_er1[2 * row1] = make_float2(c[h][8][2], c[h][8][3]);
        }
    }
}

// ---------------- layer1 agg + layer2 GEMM fused ----------------
__global__ void k_agg12(const float* __restrict__ b1, const float* __restrict__ W2,
                        const float* __restrict__ al2, const float* __restrict__ ar2) {
    __shared__ ull sW2p[32 * 32];
    __shared__ __align__(16) float srow[8][64];
    for (int e = threadIdx.x; e < 32 * 32; e += blockDim.x) {
        int k2 = e >> 5, c = e & 31;
        sW2p[e] = pack2(W2[(2 * k2) * 32 + c], W2[(2 * k2 + 1) * 32 + c]);
    }
    __syncthreads();

    int lane = threadIdx.x & 31;
    int wl = threadIdx.x >> 5;
    int warp = (blockIdx.x * blockDim.x + threadIdx.x) >> 5;
    int nw = (gridDim.x * blockDim.x) >> 5;
    int head = lane >> 4;
    float bA = b1[2 * lane], bB = b1[2 * lane + 1];
    float alv = al2[lane], arv = ar2[lane];

    for (int v = warp; v < NN; v += nw) {
        int r0 = g_rowptr[v], r1 = g_rowptr[v + 1];
        float er = g_er1[2 * v + head];
        float ssum = 0.f, accA = 0.f, accB = 0.f;
#pragma unroll 4
        for (int j = r0; j < r1; j++) {
            int s = g_esrc[j];
            float e = g_el1[2 * s + head] + er;
            e = e > 0.f ? e : 0.2f * e;                 // leaky_relu(0.2)
            float w = __expf(e);
            float2 h = *(const float2*)&g_h1[(size_t)s * 64 + 2 * lane];
            ssum += w;
            accA += w * h.x;
            accB += w * h.y;
        }
        float inv = 1.f / ssum;
        float o0 = fmaxf(accA * inv + bA, 0.f);
        float o1 = fmaxf(accB * inv + bB, 0.f);

        srow[wl][2 * lane] = o0;
        srow[wl][2 * lane + 1] = o1;
        __syncwarp();
        ull accp = 0ull;
#pragma unroll
        for (int k2 = 0; k2 < 32; k2++)
            fma2(accp, *(const ull*)&srow[wl][2 * k2], sW2p[k2 * 32 + lane]);
        __syncwarp();
        float acc = hsum2(accp);
        g_h2[(size_t)v * 32 + lane] = acc;

        float pl = acc * alv;
        float pr = acc * arv;
#pragma unroll
        for (int off = 16; off; off >>= 1) {
            pl += __shfl_xor_sync(0xffffffffu, pl, off);
            pr += __shfl_xor_sync(0xffffffffu, pr, off);
        }
        if (lane == 0) { g_el2[v] = pl; g_er2[v] = pr; }
    }
}

// ---------------- layer 2 aggregation -> final output ----------------
__global__ void k_agg2(const float* __restrict__ b2, float* __restrict__ out) {
    int lane = threadIdx.x & 31;
    int warp = (blockIdx.x * blockDim.x + threadIdx.x) >> 5;
    int nw = (gridDim.x * blockDim.x) >> 5;
    float bv = b2[lane];

    for (int v = warp; v < NN; v += nw) {
        int r0 = g_rowptr[v], r1 = g_rowptr[v + 1];
        float er = g_er2[v];
        float ssum = 0.f, acc = 0.f;
#pragma unroll 4
        for (int j = r0; j < r1; j++) {
            int s = g_esrc[j];
            float e = g_el2[s] + er;
            e = e > 0.f ? e : 0.2f * e;
            float w = __expf(e);
            float h = g_h2[(size_t)s * 32 + lane];
            ssum += w;
            acc += w * h;
        }
        out[(size_t)v * 32 + lane] = fmaxf(acc / ssum + bv, 0.f);
    }
}

// ---------------- launch ----------------
extern "C" void kernel_launch(void* const* d_in, const int* in_sizes, int n_in,
                              void* d_out, int out_size) {
    const float* feat = (const float*)d_in[0];
    const float* W1   = (const float*)d_in[1];
    const float* al1  = (const float*)d_in[2];
    const float* ar1  = (const float*)d_in[3];
    const float* b1   = (const float*)d_in[4];
    const float* W2   = (const float*)d_in[5];
    const float* al2  = (const float*)d_in[6];
    const float* ar2  = (const float*)d_in[7];
    const float* b2   = (const float*)d_in[8];
    const int*   src  = (const int*)d_in[9];
    const int*   dst  = (const int*)d_in[10];
    int E = in_sizes[9];
    if (E > EE) E = EE;
    float* out = (float*)d_out;

    static int smem_set = 0;
    if (!smem_set) {
        cudaFuncSetAttribute(k_gemm1, cudaFuncAttributeMaxDynamicSharedMemorySize, SM_TOT);
        smem_set = 1;
    }

    k_zero<<<(NN + 1 + 255) / 256, 256>>>(dst);          // 0
    k_count<<<1024, 256>>>(dst, E);                      // 1
    k_wsplit<<<36, 256>>>(W1, al1, ar1);                 // 2
    k_gemm1<<<782, 128, SM_TOT>>>(feat);                 // 3  <- profiled slot
    k_blockscan<<<SCAN_B, SCAN_T>>>();                   // 4
    k_scanbsum<<<1, 128>>>(E);                           // 5
    k_finalize<<<SCAN_B, SCAN_T>>>();                    // 6
    k_fill<<<1024, 256>>>(src, dst, E);                  // 7
    k_agg12<<<1184, 256>>>(b1, W2, al2, ar2);            // 8
    k_agg2<<<1184, 256>>>(b2, out);                      // 9
}